// round 10
// baseline (speedup 1.0000x reference)
#include <cuda_runtime.h>
#include <cstdint>

// SlideMean_Norm: out = x - clamped_sliding_mean(x, win=300) along T
// x: [32, 1, 16000, 80] float32
// window for t: [max(t-150,0), min(t+150, T-1)), count = e - s
//
// Persistent strip blocks, 620-row smem ring, cp.async double-buffered
// prefetch, span-prefix ring for O(1) window init. 320 threads (SUB=5)
// for 20 warps/SM of latency hiding.

namespace {
constexpr int T     = 16000;
constexpr int F4    = 20;       // 80 floats = 20 float4 per full row
constexpr int HALF  = 150;
constexpr int LN    = 10;       // float4 lanes per half-row (160 B)
constexpr int SUB   = 5;        // output rows per thread per iter
constexpr int CB    = 160;      // rows per iteration
constexpr int NSUB  = CB / SUB; // 32
constexpr int NTHR  = LN * NSUB;          // 320 threads = 10 warps
constexpr int L     = 4000;               // strip length
constexpr int ITERS = L / CB;             // 25
constexpr int R     = 2 * CB + 2 * HALF;  // 620-row ring
constexpr int PRO   = CB + 2 * HALF;      // 460 prologue rows
constexpr int SPAN  = 10;                 // rows per span
constexpr int NSP_I = CB / SPAN;          // 16 spans per iter
constexpr int NSPAN_PRO = PRO / SPAN;     // 46
constexpr int SPR   = 64;                 // SP ring (pow2)
constexpr int WSP   = 2 * HALF / SPAN;    // 30 spans per window
constexpr float INV_FULL = 1.0f / 300.0f;
constexpr int SMEM_BYTES =
    (R * LN + SPR * LN + 2 * NSP_I * LN) * (int)sizeof(float4); // 114,560 B
}

__device__ __forceinline__ float4 operator+(float4 a, float4 b) {
    return make_float4(a.x+b.x, a.y+b.y, a.z+b.z, a.w+b.w);
}
__device__ __forceinline__ float4 operator-(float4 a, float4 b) {
    return make_float4(a.x-b.x, a.y-b.y, a.z-b.z, a.w-b.w);
}
__device__ __forceinline__ void operator+=(float4& a, float4 b) { a = a + b; }
__device__ __forceinline__ void operator-=(float4& a, float4 b) { a = a - b; }
__device__ __forceinline__ float4 f4_fnms(float4 x, float4 ws, float inv) {
    return make_float4(fmaf(-ws.x, inv, x.x), fmaf(-ws.y, inv, x.y),
                       fmaf(-ws.z, inv, x.z), fmaf(-ws.w, inv, x.w));
}

__device__ __forceinline__ void cpa16(uint32_t dst, const float4* src, bool valid) {
    int sz = valid ? 16 : 0;   // src-size 0 => zero-fill
    asm volatile("cp.async.cg.shared.global [%0], [%1], 16, %2;\n"
                 :: "r"(dst), "l"(src), "r"(sz));
}
__device__ __forceinline__ void cpa_commit() {
    asm volatile("cp.async.commit_group;\n");
}
template <int N>
__device__ __forceinline__ void cpa_wait() {
    asm volatile("cp.async.wait_group %0;\n" :: "n"(N));
}

__global__ __launch_bounds__(NTHR, 2) void slide_ring_kernel(
    const float4* __restrict__ x, float4* __restrict__ out)
{
    extern __shared__ float4 smem[];
    float4* __restrict__ tile = smem;                   // [R][LN]
    float4* __restrict__ sp   = smem + R * LN;          // [SPR][LN] span prefix
    float4* __restrict__ scrA = sp + SPR * LN;          // [NSP_I][LN]
    float4* __restrict__ scrB = scrA + NSP_I * LN;      // [NSP_I][LN]

    const int ln  = threadIdx.x;     // 0..9
    const int ty  = threadIdx.y;     // 0..31
    const int tid = ty * LN + ln;
    const int S0  = blockIdx.x * L;
    const int b   = blockIdx.y;
    const int hoff = blockIdx.z * LN;
    const int gfirst = S0 - HALF;

    const float4* __restrict__ xb = x   + (size_t)b * T * F4 + hoff;
    float4*       __restrict__ ob = out + (size_t)b * T * F4 + hoff;

    const uint32_t tile_sa = (uint32_t)__cvta_generic_to_shared(tile);
    const float4 zero = make_float4(0.f, 0.f, 0.f, 0.f);

    // ---- async load of local rows [l0, l0+nrows) into ring ----
    auto load_rows = [&](int l0, int nrows) {
        const int ring0 = l0 % R;
        for (int r = ty; r < nrows; r += NSUB) {
            int rg = ring0 + r; if (rg >= R) rg -= R;
            int g  = gfirst + l0 + r;
            bool v = (g >= 0) & (g < T);
            cpa16(tile_sa + (uint32_t)(rg * LN + ln) * 16,
                  xb + (size_t)(v ? g : 0) * F4 + ln, v);
        }
    };

    // ---- build nspans 10-row spans for rows [l0,...), scan, append to SP.
    //      J = global span index of predecessor (SP[J] must exist). ----
    auto extend_spans = [&](int l0, int nspans, int J) {
        float4 s = zero;
        if (ty < nspans) {
            int rb = (l0 % R) + ty * SPAN; if (rb >= R) rb -= R;
            const float4* __restrict__ tp = tile + rb * LN + ln;
            #pragma unroll
            for (int k = 0; k < SPAN; ++k) s += tp[k * LN];
        }
        if (ty < NSP_I) scrA[ty * LN + ln] = s;
        __syncthreads();
        float4 base = sp[(J & (SPR - 1)) * LN + ln];
        if (ty < NSP_I) {
            if (ty >= 1) s += scrA[(ty - 1) * LN + ln];
            scrB[ty * LN + ln] = s;
        }
        __syncthreads();
        if (ty < NSP_I) {
            if (ty >= 2) s += scrB[(ty - 2) * LN + ln];
            scrA[ty * LN + ln] = s;
        }
        __syncthreads();
        if (ty < NSP_I) {
            if (ty >= 4) s += scrA[(ty - 4) * LN + ln];
            scrB[ty * LN + ln] = s;
        }
        __syncthreads();
        if (ty < NSP_I) {
            if (ty >= 8) s += scrB[(ty - 8) * LN + ln];
            if (ty < nspans)
                sp[((J + 1 + ty) & (SPR - 1)) * LN + ln] = base + s;
        }
        __syncthreads();
    };

    // ---- prologue ----
    load_rows(0, PRO);        cpa_commit();
    load_rows(PRO, CB);       cpa_commit();
    cpa_wait<1>();
    __syncthreads();
    if (tid < LN) sp[tid] = zero;     // SP[0] = 0
    __syncthreads();
    extend_spans(0,   NSP_I, 0);                 // spans  0..15 -> SP[1..16]
    extend_spans(160, NSP_I, 16);                // spans 16..31 -> SP[17..32]
    extend_spans(320, NSPAN_PRO - 2 * NSP_I, 32);// spans 32..45 -> SP[33..46]

    for (int i = 0; i < ITERS; ++i) {
        // ---- compute outputs [S0+i*CB, +CB) ----
        {
            const int tg0 = S0 + i * CB + ty * SUB;
            const int lw  = i * CB + ty * SUB;   // local window start

            // window init
            float4 ws;
            if ((ty & 1) == 0) {
                // span-aligned: lw multiple of 10
                const int m0 = i * NSP_I + (ty >> 1);
                ws = sp[((m0 + WSP) & (SPR - 1)) * LN + ln]
                   - sp[(m0 & (SPR - 1)) * LN + ln];
            } else {
                // lw = 10a+5: interior spans a+1..a+29 cover [lw+5, lw+295);
                // head rows [lw, lw+5), tail rows [lw+295, lw+300).
                const int a = i * NSP_I + (ty >> 1);
                ws = sp[((a + WSP) & (SPR - 1)) * LN + ln]
                   - sp[((a + 1) & (SPR - 1)) * LN + ln];
                int rh  = lw % R;                        // head [lw, lw+5)
                int rt2 = (lw + 2 * HALF - SUB) % R;     // tail [lw+295, lw+300)
                const float4* __restrict__ ph = tile + rh * LN + ln;
                const float4* __restrict__ pq = tile + rt2 * LN + ln;
                #pragma unroll
                for (int k = 0; k < SUB; ++k) ws += ph[k * LN] + pq[k * LN];
            }

            int rc = (lw + HALF) % R;                 // multiple of 5
            int rl = rc + HALF; if (rl >= R) rl -= R;
            int rt = rc - HALF; if (rt < 0)  rt += R;
            // 5-row segments never wrap (bases multiples of 5, 5 | R)
            const float4* __restrict__ pc = tile + rc * LN + ln;
            const float4* __restrict__ pl = tile + rl * LN + ln;
            const float4* __restrict__ pt = tile + rt * LN + ln;
            float4* __restrict__ op = ob + (size_t)tg0 * F4 + ln;

            const bool lo = (tg0 < HALF);
            const bool hi = (tg0 >= T - HALF);
            if (!lo && !hi) {
                #pragma unroll
                for (int k = 0; k < SUB; ++k) {
                    float4 xv = pc[k * LN];
                    __stcs(op + (size_t)k * F4, f4_fnms(xv, ws, INV_FULL));
                    ws += pl[k * LN] - pt[k * LN];
                }
            } else {
                float4 xl = zero;
                if (hi) xl = tile[((T - 1 - gfirst) % R) * LN + ln];
                #pragma unroll
                for (int k = 0; k < SUB; ++k) {
                    const int t = tg0 + k;
                    int s = t - HALF; if (s < 0) s = 0;
                    int e = t + HALF; if (e > T - 1) e = T - 1;
                    float inv = 1.0f / (float)(e - s);
                    float4 wsc = ws;
                    if (t >= T - HALF) wsc -= xl;
                    float4 xv = pc[k * LN];
                    __stcs(op + (size_t)k * F4, f4_fnms(xv, wsc, inv));
                    ws += pl[k * LN] - pt[k * LN];
                }
            }
        }

        // ---- pipeline turn-over ----
        if (i + 1 < ITERS) {
            cpa_wait<0>();        // group for iter i+1 arrived
            __syncthreads();      // all compute readers done before reuse
            extend_spans(PRO + i * CB, NSP_I, NSPAN_PRO + i * NSP_I);
            if (i + 2 < ITERS) {
                load_rows(PRO + (i + 1) * CB, CB);
                cpa_commit();
            }
        }
    }
}

extern "C" void kernel_launch(void* const* d_in, const int* in_sizes, int n_in,
                              void* d_out, int out_size)
{
    const float4* x = (const float4*)d_in[0];
    float4* out = (float4*)d_out;

    static bool attr_set = false;
    if (!attr_set) {
        cudaFuncSetAttribute(slide_ring_kernel,
                             cudaFuncAttributeMaxDynamicSharedMemorySize,
                             SMEM_BYTES);
        attr_set = true;
    }

    dim3 blk(LN, NSUB);            // 320 threads = 10 warps
    dim3 grid(T / L, 32, 2);       // 4 strips x 32 batches x 2 halves = 256
    slide_ring_kernel<<<grid, blk, SMEM_BYTES>>>(x, out);
}